// round 11
// baseline (speedup 1.0000x reference)
#include <cuda_runtime.h>
#include <cuda_bf16.h>

#define BATCH 4096
#define NHID  512
#define BR    32
#define NBKT  1024   // bucket key = lab>>5 ; node2 = 33+bkt, node1 = 1+(bkt>>5)

#define L0_BLOCKS 512
#define L1_SLOTS  544
#define L2_SLOTS  2048

#define SCAT_BLOCKS 16
#define LV0_BASE (1 + SCAT_BLOCKS)                 // 17
#define LV1_BASE (LV0_BASE + L0_BLOCKS)            // 529
#define LV2_BASE (LV1_BASE + L1_SLOTS)             // 1073
#define GRID_TOTAL (LV2_BASE + L2_SLOTS)           // 3121

__device__ int   d_start[NBKT + 1];
__device__ int   d_cur[NBKT];
__device__ int   d_perm[BATCH];
__device__ int   d_g1off[33];
__device__ int   d_g2off[NBKT + 1];
__device__ float d_p[3][BATCH];
__device__ volatile int d_flag1;     // tables done
__device__ volatile int d_flag2;     // scatter done
__device__ int   d_scat_done;
__device__ int   d_all_done;

// ---------------- publish / wait helpers (device-side dependencies) ----------------
__device__ __forceinline__ void wait_flag(volatile int* f)
{
    if (threadIdx.x == 0) {
        while (*f == 0) __nanosleep(64);
        __threadfence();                    // acquire
    }
    __syncthreads();
}

// ---------------- tables (128 threads): hist + scans + task tables ----------------
__device__ __forceinline__ void do_tables(const int* __restrict__ labels,
                                          int* __restrict__ hist,   // [1024] smem
                                          int* __restrict__ scr)    // [>=48] smem
{
    const int t = threadIdx.x;              // 0..127
    const int lane = t & 31, wid = t >> 5;

    #pragma unroll
    for (int j = 0; j < 8; j++) hist[j * 128 + t] = 0;
    __syncthreads();
    #pragma unroll
    for (int i = 0; i < 32; i++)
        atomicAdd(&hist[labels[i * 128 + t] >> 5], 1);
    __syncthreads();

    // thread t owns buckets [8t, 8t+8)
    int h[8], tot = 0;
    #pragma unroll
    for (int j = 0; j < 8; j++) { h[j] = hist[t * 8 + j]; tot += h[j]; }

    // ---- pass 1: exclusive scan of sample counts -> d_start / d_cur ----
    int inc = tot;
    #pragma unroll
    for (int o = 1; o < 32; o <<= 1) {
        int u = __shfl_up_sync(0xffffffffu, inc, o);
        if (lane >= o) inc += u;
    }
    if (lane == 31) scr[wid] = inc;
    __syncthreads();
    if (t == 0) { int a = 0; for (int w = 0; w < 4; w++) { int v = scr[w]; scr[w] = a; a += v; } }
    __syncthreads();
    int run = scr[wid] + inc - tot;
    #pragma unroll
    for (int j = 0; j < 8; j++) { d_start[t * 8 + j] = run; d_cur[t * 8 + j] = run; run += h[j]; }
    if (t == 127) d_start[NBKT] = BATCH;

    // ---- pass 2: level-2 group prefix (ceil(h/4)) -> d_g2off ----
    int g[8], gtot = 0;
    #pragma unroll
    for (int j = 0; j < 8; j++) { g[j] = (h[j] + 3) >> 2; gtot += g[j]; }
    int inc2 = gtot;
    #pragma unroll
    for (int o = 1; o < 32; o <<= 1) {
        int u = __shfl_up_sync(0xffffffffu, inc2, o);
        if (lane >= o) inc2 += u;
    }
    if (lane == 31) scr[8 + wid] = inc2;
    __syncthreads();
    if (t == 0) { int a = 0; for (int w = 0; w < 4; w++) { int v = scr[8 + w]; scr[8 + w] = a; a += v; } }
    __syncthreads();
    int run2 = scr[8 + wid] + inc2 - gtot;
    #pragma unroll
    for (int j = 0; j < 8; j++) { d_g2off[t * 8 + j] = run2; run2 += g[j]; }
    if (t == 127) d_g2off[NBKT] = run2;

    // ---- level-1 group prefix: node n = buckets [32n, 32n+32) = threads 4n..4n+3 ----
    int nsum = tot;
    nsum += __shfl_xor_sync(0xffffffffu, nsum, 1);
    nsum += __shfl_xor_sync(0xffffffffu, nsum, 2);
    if ((t & 3) == 0) scr[16 + (t >> 2)] = (nsum + 7) >> 3;
    __syncthreads();
    if (t == 0) {
        int a = 0; d_g1off[0] = 0;
        #pragma unroll
        for (int n = 0; n < 32; n++) { a += scr[16 + n]; d_g1off[n + 1] = a; }
    }
}

// largest k with off[k] <= i
__device__ __forceinline__ int find_bucket(const int* __restrict__ off, int n, int i)
{
    int lo = 0, hi = n;
    while (lo + 1 < hi) {
        int mid = (lo + hi) >> 1;
        if (off[mid] <= i) lo = mid; else hi = mid;
    }
    return lo;
}

// ---- shared prologue: fetch sample ids/steps and stage x ----
template<int SMAX>
__device__ __forceinline__ void stage_samples(
    const float* __restrict__ x, const int* __restrict__ labels,
    float4* __restrict__ xsv, int* __restrict__ sid_sm, int* __restrict__ step_sm,
    int shift, int base, int S, bool use_perm)
{
    const int tid = threadIdx.x;
    if (tid < S) {
        const int sb = use_perm ? d_perm[base + tid] : (base + tid);
        sid_sm[tid]  = sb;
        step_sm[tid] = (labels[sb] >> shift) & 31;
    }
    __syncthreads();
    #pragma unroll
    for (int s = 0; s < SMAX; s++) {
        if (s < S) {
            const float4* xg = reinterpret_cast<const float4*>(x + (size_t)sid_sm[s] * NHID);
            xsv[s * 128 + tid] = xg[tid];
        }
    }
    __syncthreads();
}

// ---------------- scalar-W group task (levels 0/1) ----------------
template<int SMAX, int LVL>
__device__ __forceinline__ void process_group_scalar(
    const float* __restrict__ x, const int* __restrict__ labels,
    const float* __restrict__ W,
    float4* __restrict__ xsv, float* __restrict__ part,
    int* __restrict__ sid_sm, int* __restrict__ step_sm,
    int node, int shift, int base, int S, bool use_perm)
{
    const int tid  = threadIdx.x;
    const int warp = tid >> 5;
    const int lane = tid & 31;

    stage_samples<SMAX>(x, labels, xsv, sid_sm, step_sm, shift, base, S, use_perm);

    const float* __restrict__ Wq =
        W + (size_t)node * (NHID * BR) + (warp * 128) * BR + lane;

    float acc[SMAX];
    #pragma unroll
    for (int s = 0; s < SMAX; s++) acc[s] = 0.f;

    #pragma unroll 4
    for (int t = 0; t < 32; t++) {
        const float w0 = __ldg(Wq + (4 * t + 0) * BR);
        const float w1 = __ldg(Wq + (4 * t + 1) * BR);
        const float w2 = __ldg(Wq + (4 * t + 2) * BR);
        const float w3 = __ldg(Wq + (4 * t + 3) * BR);
        #pragma unroll
        for (int s = 0; s < SMAX; s++) {
            const float4 xq = xsv[s * 128 + warp * 32 + t];   // broadcast LDS.128
            acc[s] = fmaf(xq.x, w0, acc[s]);
            acc[s] = fmaf(xq.y, w1, acc[s]);
            acc[s] = fmaf(xq.z, w2, acc[s]);
            acc[s] = fmaf(xq.w, w3, acc[s]);
        }
    }

    #pragma unroll
    for (int s = 0; s < SMAX; s++)
        part[(warp * SMAX + s) * 32 + lane] = acc[s];
    __syncthreads();

    #pragma unroll
    for (int si = warp; si < SMAX; si += 4) {
        float logit = part[(0 * SMAX + si) * 32 + lane]
                    + part[(1 * SMAX + si) * 32 + lane]
                    + part[(2 * SMAX + si) * 32 + lane]
                    + part[(3 * SMAX + si) * 32 + lane];
        float m = logit;
        #pragma unroll
        for (int o = 16; o; o >>= 1) m = fmaxf(m, __shfl_xor_sync(0xffffffffu, m, o));
        const float e = __expf(logit - m);
        float ssum = e;
        #pragma unroll
        for (int o = 16; o; o >>= 1) ssum += __shfl_xor_sync(0xffffffffu, ssum, o);
        if (si < S) {
            const float es = __shfl_sync(0xffffffffu, e, step_sm[si]);
            if (lane == 0) d_p[LVL][sid_sm[si]] = es / ssum;
        }
    }
}

// ---------------- float4-W group task (level 2) ----------------
__device__ __forceinline__ void process_group_vec4(
    const float* __restrict__ x, const int* __restrict__ labels,
    const float* __restrict__ W,
    float4* __restrict__ xsv, float* __restrict__ part,
    int* __restrict__ sid_sm, int* __restrict__ step_sm,
    int node, int base, int S)
{
    const int tid  = threadIdx.x;
    const int warp = tid >> 5;
    const int lane = tid & 31;
    const int g    = lane >> 3;
    const int ci   = lane & 7;

    stage_samples<4>(x, labels, xsv, sid_sm, step_sm, /*shift=*/0, base, S, true);
    const float* xsf = reinterpret_cast<const float*>(xsv);

    const float4* __restrict__ Wv =
        reinterpret_cast<const float4*>(W + (size_t)node * (NHID * BR))
        + (warp * 128) * 8 + ci;

    float4 acc[4];
    #pragma unroll
    for (int s = 0; s < 4; s++) acc[s] = make_float4(0.f, 0.f, 0.f, 0.f);

    #pragma unroll 8
    for (int t = 0; t < 32; t++) {
        const int h = 4 * t + g;
        const float4 w = __ldg(Wv + h * 8);
        #pragma unroll
        for (int s = 0; s < 4; s++) {
            const float xv = xsf[s * 512 + warp * 128 + h];
            acc[s].x = fmaf(xv, w.x, acc[s].x);
            acc[s].y = fmaf(xv, w.y, acc[s].y);
            acc[s].z = fmaf(xv, w.z, acc[s].z);
            acc[s].w = fmaf(xv, w.w, acc[s].w);
        }
    }

    #pragma unroll
    for (int o = 8; o <= 16; o <<= 1) {
        #pragma unroll
        for (int s = 0; s < 4; s++) {
            acc[s].x += __shfl_xor_sync(0xffffffffu, acc[s].x, o);
            acc[s].y += __shfl_xor_sync(0xffffffffu, acc[s].y, o);
            acc[s].z += __shfl_xor_sync(0xffffffffu, acc[s].z, o);
            acc[s].w += __shfl_xor_sync(0xffffffffu, acc[s].w, o);
        }
    }
    if (g == 0) {
        float4* part4 = reinterpret_cast<float4*>(part);
        #pragma unroll
        for (int s = 0; s < 4; s++)
            part4[(warp * 4 + s) * 8 + ci] = acc[s];
    }
    __syncthreads();

    const int si = warp;
    float logit = part[(0 * 4 + si) * 32 + lane]
                + part[(1 * 4 + si) * 32 + lane]
                + part[(2 * 4 + si) * 32 + lane]
                + part[(3 * 4 + si) * 32 + lane];
    float m = logit;
    #pragma unroll
    for (int o = 16; o; o >>= 1) m = fmaxf(m, __shfl_xor_sync(0xffffffffu, m, o));
    const float e = __expf(logit - m);
    float ssum = e;
    #pragma unroll
    for (int o = 16; o; o >>= 1) ssum += __shfl_xor_sync(0xffffffffu, ssum, o);
    if (si < S) {
        const float es = __shfl_sync(0xffffffffu, e, step_sm[si]);
        if (lane == 0) d_p[2][sid_sm[si]] = es / ssum;
    }
}

// ---------------- mega kernel: tables + scatter + all levels, flag-synced ----------------
__global__ __launch_bounds__(128)
void mega_kernel(const float* __restrict__ x,
                 const int* __restrict__ labels,
                 const float* __restrict__ W)
{
    __shared__ float4 xsv[8 * 128];        // 16 KB (tables reuses as hist)
    __shared__ float  part[4 * 8 * 32];    // 4 KB  (tables reuses as scratch)
    __shared__ int    sid_sm[8];
    __shared__ int    step_sm[8];

    const int blk = blockIdx.x;

    if (blk == 0) {
        // -------- tables producer --------
        do_tables(labels, reinterpret_cast<int*>(xsv), reinterpret_cast<int*>(part));
        __threadfence();
        __syncthreads();
        if (threadIdx.x == 0) d_flag1 = 1;
    } else if (blk <= SCAT_BLOCKS) {
        // -------- scatter (needs d_start/d_cur) --------
        wait_flag(&d_flag1);
        const int i0 = (blk - 1) * 256 + threadIdx.x;
        int p = atomicAdd(&d_cur[labels[i0] >> 5], 1);
        d_perm[p] = i0;
        const int i1 = i0 + 128;
        p = atomicAdd(&d_cur[labels[i1] >> 5], 1);
        d_perm[p] = i1;
        __threadfence();
        __syncthreads();
        if (threadIdx.x == 0) {
            if (atomicAdd(&d_scat_done, 1) == SCAT_BLOCKS - 1) d_flag2 = 1;
        }
    } else if (blk < LV1_BASE) {
        // -------- level 0: independent of sort, overlaps it --------
        process_group_scalar<8, 0>(x, labels, W, xsv, part, sid_sm, step_sm,
                                   /*node=*/0, /*shift=*/10, (blk - LV0_BASE) * 8, 8, false);
    } else if (blk < LV2_BASE) {
        // -------- level 1 --------
        wait_flag(&d_flag2);
        const int i = blk - LV1_BASE;
        if (i < d_g1off[32]) {
            const int g    = find_bucket(d_g1off, 32, i);
            const int base = d_start[g * 32] + (i - d_g1off[g]) * 8;
            const int S    = min(8, d_start[g * 32 + 32] - base);
            process_group_scalar<8, 1>(x, labels, W, xsv, part, sid_sm, step_sm,
                                       1 + g, /*shift=*/5, base, S, true);
        }
    } else {
        // -------- level 2 --------
        wait_flag(&d_flag2);
        const int i = blk - LV2_BASE;
        if (i < d_g2off[NBKT]) {
            const int k    = find_bucket(d_g2off, NBKT, i);
            const int base = d_start[k] + (i - d_g2off[k]) * 4;
            const int S    = min(4, d_start[k + 1] - base);
            process_group_vec4(x, labels, W, xsv, part, sid_sm, step_sm,
                               33 + k, base, S);
        }
    }

    // -------- completion count; last block resets flags for the next replay --------
    __syncthreads();
    if (threadIdx.x == 0) {
        __threadfence();
        if (atomicAdd(&d_all_done, 1) == GRID_TOTAL - 1) {
            d_flag1 = 0;
            d_flag2 = 0;
            d_scat_done = 0;
            d_all_done = 0;
        }
    }
}

__global__ __launch_bounds__(256)
void combine_kernel(float* __restrict__ out)
{
    const int b = blockIdx.x * 256 + threadIdx.x;
    out[b] = d_p[0][b] * d_p[1][b] * d_p[2][b];
}

extern "C" void kernel_launch(void* const* d_in, const int* in_sizes, int n_in,
                              void* d_out, int out_size)
{
    const float* x      = (const float*)d_in[0];   // [4096, 512] f32
    const int*   labels = (const int*)d_in[1];     // [4096] i32
    const float* W      = (const float*)d_in[2];   // [1057, 512, 32] f32
    float*       out    = (float*)d_out;           // [4096] f32

    mega_kernel   <<<GRID_TOTAL, 128>>>(x, labels, W);
    combine_kernel<<<BATCH / 256, 256>>>(out);
}

// round 12
// speedup vs baseline: 1.0495x; 1.0495x over previous
#include <cuda_runtime.h>
#include <cuda_bf16.h>
#include <cstdint>

#define BATCH 4096
#define NHID  512
#define BR    32
#define NBKT  1024   // bucket key = lab>>5 ; node2 = 33+bkt, node1 = 1+(bkt>>5)

#define L0_BLOCKS 512          // 4096/8 groups, S=8
#define L1_SLOTS  544          // >= 32 + 4096/8 worst-case level-1 groups (S=8)
#define L2_SLOTS  2048         // >= 1024 + 4096/4 worst-case level-2 groups (S=4)

__device__ int   d_start[NBKT + 1];
__device__ int   d_cur[NBKT];
__device__ int   d_perm[BATCH];
__device__ int   d_g1off[33];        // prefix of level-1 group counts per node
__device__ int   d_g2off[NBKT + 1];  // prefix of level-2 group counts per bucket
__device__ float d_p[3][BATCH];      // per-level probabilities

// ---------------- tables kernel: hist + scans + task tables (NO scatter) ----------------
__global__ __launch_bounds__(1024, 1)
void tables_kernel(const int* __restrict__ labels)
{
    __shared__ int hist[NBKT];
    __shared__ int wsum[32];
    __shared__ int l1cnt[32];

    const int t    = threadIdx.x;
    const int wid  = t >> 5;
    const int lane = t & 31;

    hist[t] = 0;
    __syncthreads();
    #pragma unroll
    for (int i = 0; i < 4; i++)
        atomicAdd(&hist[labels[t + i * 1024] >> 5], 1);
    __syncthreads();

    // exclusive scan of hist (warp scan + warp-sum scan)
    const int h = hist[t];
    int v = h;
    #pragma unroll
    for (int o = 1; o < 32; o <<= 1) {
        int u = __shfl_up_sync(0xffffffffu, v, o);
        if (lane >= o) v += u;
    }
    if (lane == 31) wsum[wid] = v;
    __syncthreads();
    if (wid == 0) {
        int w = wsum[lane];
        #pragma unroll
        for (int o = 1; o < 32; o <<= 1) {
            int u = __shfl_up_sync(0xffffffffu, w, o);
            if (lane >= o) w += u;
        }
        wsum[lane] = w;
    }
    __syncthreads();
    const int excl = v + (wid > 0 ? wsum[wid - 1] : 0) - h;
    d_start[t] = excl;
    d_cur[t]   = excl;
    if (t == 0) d_start[NBKT] = BATCH;
    __syncthreads();

    // level-2 group prefix: ceil(n_bkt/4)
    int g2 = (h + 3) >> 2;
    int v2 = g2;
    #pragma unroll
    for (int o = 1; o < 32; o <<= 1) {
        int u = __shfl_up_sync(0xffffffffu, v2, o);
        if (lane >= o) v2 += u;
    }
    if (lane == 31) wsum[wid] = v2;
    __syncthreads();
    if (wid == 0) {
        int w = wsum[lane];
        #pragma unroll
        for (int o = 1; o < 32; o <<= 1) {
            int u = __shfl_up_sync(0xffffffffu, w, o);
            if (lane >= o) w += u;
        }
        wsum[lane] = w;
    }
    __syncthreads();
    const int incl2 = v2 + (wid > 0 ? wsum[wid - 1] : 0);
    d_g2off[t] = incl2 - g2;
    if (t == 1023) d_g2off[NBKT] = incl2;

    // level-1 group prefix: node w owns buckets [32w, 32w+32)
    {
        int c = hist[wid * 32 + lane];
        #pragma unroll
        for (int o = 16; o; o >>= 1) c += __shfl_xor_sync(0xffffffffu, c, o);
        if (lane == 0) l1cnt[wid] = (c + 7) >> 3;
    }
    __syncthreads();
    if (t == 0) {
        int acc = 0;
        d_g1off[0] = 0;
        #pragma unroll
        for (int g = 0; g < 32; g++) { acc += l1cnt[g]; d_g1off[g + 1] = acc; }
    }
}

// ---------------- scatter kernel: 16 blocks spread the scattered STGs ----------------
__global__ __launch_bounds__(256)
void scatter_kernel(const int* __restrict__ labels)
{
    const int i = blockIdx.x * 256 + threadIdx.x;
    const int p = atomicAdd(&d_cur[labels[i] >> 5], 1);
    d_perm[p] = i;
}

// largest k with off[k] <= i
__device__ __forceinline__ int find_bucket(const int* __restrict__ off, int n, int i)
{
    int lo = 0, hi = n;
    while (lo + 1 < hi) {
        int mid = (lo + hi) >> 1;
        if (off[mid] <= i) lo = mid; else hi = mid;
    }
    return lo;
}

// ---- shared prologue: fetch sample ids/steps and stage x -------------------------
template<int SMAX>
__device__ __forceinline__ void stage_samples(
    const float* __restrict__ x, const int* __restrict__ labels,
    float4* __restrict__ xsv, int* __restrict__ sid_sm, int* __restrict__ step_sm,
    int shift, int base, int S, bool use_perm)
{
    const int tid = threadIdx.x;
    if (tid < S) {
        const int sb = use_perm ? d_perm[base + tid] : (base + tid);
        sid_sm[tid]  = sb;
        step_sm[tid] = (labels[sb] >> shift) & 31;
    }
    __syncthreads();
    #pragma unroll
    for (int s = 0; s < SMAX; s++) {
        if (s < S) {
            const float4* xg = reinterpret_cast<const float4*>(x + (size_t)sid_sm[s] * NHID);
            xsv[s * 128 + tid] = xg[tid];
        }
    }
    __syncthreads();
}

// ---------------- FMA2 group task: SMAX samples x one node, 4-warp h-split ------------
// Pair adjacent h values: the per-sample LDS.128 of x[4t..4t+3] is reinterpreted as
// two packed f32x2 operands (free), W packs with 2 mov.b64 per t (amortized over all
// samples), and fma.rn.f32x2 halves the FMA issue count. acc2 lanes carry even-h /
// odd-h partial sums, folded by one add at the end.
template<int SMAX, int LVL>
__device__ __forceinline__ void process_group_fma2(
    const float* __restrict__ x, const int* __restrict__ labels,
    const float* __restrict__ W,
    float4* __restrict__ xsv, float* __restrict__ part,
    int* __restrict__ sid_sm, int* __restrict__ step_sm,
    int node, int shift, int base, int S, bool use_perm)
{
    const int tid  = threadIdx.x;
    const int warp = tid >> 5;
    const int lane = tid & 31;

    stage_samples<SMAX>(x, labels, xsv, sid_sm, step_sm, shift, base, S, use_perm);

    const float* __restrict__ Wq =
        W + (size_t)node * (NHID * BR) + (warp * 128) * BR + lane;

    const uint32_t xbase =
        (uint32_t)__cvta_generic_to_shared(xsv) + (warp * 32) * 16;

    uint64_t acc2[SMAX];
    #pragma unroll
    for (int s = 0; s < SMAX; s++) acc2[s] = 0ull;

    #pragma unroll 4
    for (int t = 0; t < 32; t++) {
        const float w0 = __ldg(Wq + (4 * t + 0) * BR);
        const float w1 = __ldg(Wq + (4 * t + 1) * BR);
        const float w2 = __ldg(Wq + (4 * t + 2) * BR);
        const float w3 = __ldg(Wq + (4 * t + 3) * BR);
        uint64_t w01, w23;
        asm("mov.b64 %0, {%1, %2};" : "=l"(w01) : "f"(w0), "f"(w1));
        asm("mov.b64 %0, {%1, %2};" : "=l"(w23) : "f"(w2), "f"(w3));
        #pragma unroll
        for (int s = 0; s < SMAX; s++) {
            uint64_t x01, x23;
            const uint32_t a = xbase + (s * 128 + t) * 16;
            asm volatile("ld.shared.v2.u64 {%0, %1}, [%2];"
                         : "=l"(x01), "=l"(x23) : "r"(a));
            asm("fma.rn.f32x2 %0, %1, %2, %0;" : "+l"(acc2[s]) : "l"(x01), "l"(w01));
            asm("fma.rn.f32x2 %0, %1, %2, %0;" : "+l"(acc2[s]) : "l"(x23), "l"(w23));
        }
    }

    #pragma unroll
    for (int s = 0; s < SMAX; s++) {
        float lo, hi;
        asm("mov.b64 {%0, %1}, %2;" : "=f"(lo), "=f"(hi) : "l"(acc2[s]));
        part[(warp * SMAX + s) * 32 + lane] = lo + hi;
    }
    __syncthreads();

    #pragma unroll
    for (int si = warp; si < SMAX; si += 4) {
        float logit = part[(0 * SMAX + si) * 32 + lane]
                    + part[(1 * SMAX + si) * 32 + lane]
                    + part[(2 * SMAX + si) * 32 + lane]
                    + part[(3 * SMAX + si) * 32 + lane];
        float m = logit;
        #pragma unroll
        for (int o = 16; o; o >>= 1) m = fmaxf(m, __shfl_xor_sync(0xffffffffu, m, o));
        const float e = __expf(logit - m);
        float ssum = e;
        #pragma unroll
        for (int o = 16; o; o >>= 1) ssum += __shfl_xor_sync(0xffffffffu, ssum, o);
        if (si < S) {
            const float es = __shfl_sync(0xffffffffu, e, step_sm[si]);
            if (lane == 0) d_p[LVL][sid_sm[si]] = es / ssum;
        }
    }
}

// ---------------- unified levels kernel (R5/R9 macro-structure) ----------------
__global__ __launch_bounds__(128)
void levels_kernel(const float* __restrict__ x,
                   const int* __restrict__ labels,
                   const float* __restrict__ W)
{
    __shared__ float4 xsv[8 * 128];        // 16 KB
    __shared__ float  part[4 * 8 * 32];    // 4 KB
    __shared__ int    sid_sm[8];
    __shared__ int    step_sm[8];

    const int blk = blockIdx.x;

    if (blk < L0_BLOCKS) {
        process_group_fma2<8, 0>(x, labels, W, xsv, part, sid_sm, step_sm,
                                 /*node=*/0, /*shift=*/10, blk * 8, 8, false);
    } else if (blk < L0_BLOCKS + L1_SLOTS) {
        const int i = blk - L0_BLOCKS;
        if (i >= d_g1off[32]) return;
        const int g    = find_bucket(d_g1off, 32, i);
        const int base = d_start[g * 32] + (i - d_g1off[g]) * 8;
        const int S    = min(8, d_start[g * 32 + 32] - base);
        process_group_fma2<8, 1>(x, labels, W, xsv, part, sid_sm, step_sm,
                                 1 + g, /*shift=*/5, base, S, true);
    } else {
        const int i = blk - (L0_BLOCKS + L1_SLOTS);
        if (i >= d_g2off[NBKT]) return;
        const int k    = find_bucket(d_g2off, NBKT, i);
        const int base = d_start[k] + (i - d_g2off[k]) * 4;
        const int S    = min(4, d_start[k + 1] - base);
        process_group_fma2<4, 2>(x, labels, W, xsv, part, sid_sm, step_sm,
                                 33 + k, /*shift=*/0, base, S, true);
    }
}

__global__ __launch_bounds__(256)
void combine_kernel(float* __restrict__ out)
{
    const int b = blockIdx.x * 256 + threadIdx.x;
    out[b] = d_p[0][b] * d_p[1][b] * d_p[2][b];
}

extern "C" void kernel_launch(void* const* d_in, const int* in_sizes, int n_in,
                              void* d_out, int out_size)
{
    const float* x      = (const float*)d_in[0];   // [4096, 512] f32
    const int*   labels = (const int*)d_in[1];     // [4096] i32
    const float* W      = (const float*)d_in[2];   // [1057, 512, 32] f32
    float*       out    = (float*)d_out;           // [4096] f32

    tables_kernel <<<1, 1024>>>(labels);
    scatter_kernel<<<16, 256>>>(labels);
    levels_kernel <<<L0_BLOCKS + L1_SLOTS + L2_SLOTS, 128>>>(x, labels, W);
    combine_kernel<<<BATCH / 256, 256>>>(out);
}